// round 17
// baseline (speedup 1.0000x reference)
#include <cuda_runtime.h>
#include <cstdint>

// Problem shape (fixed by the reference): B=8, S=512, V=32000, M=32, PAD_ID=1
// NOTE: jax without x64 silently makes "int64" inputs int32 — a and mask are int32.
#define BB 8
#define SS 512
#define VV 32000
#define MM 32
#define PAD_ID 1

#define ROWS (BB * SS)            // 4096
#define WARPS_PER_BLOCK 2
#define THREADS (WARPS_PER_BLOCK * 32)        // 64
#define NBLOCKS (ROWS / WARPS_PER_BLOCK)      // 2048
#define NSLOTS 256                // 16 rows per slot; 32 consecutive slots per b

// Scratch (device-side allocation is forbidden -> __device__ globals).
// Zero-initialized at load; the finalize warp re-zeroes after each run so
// every graph replay starts from zeros (deterministic).
__device__ float g_partials[NSLOTS];
__device__ unsigned int g_done = 0;

#define NEG_INF (-__int_as_float(0x7f800000))

// One fully independent warp per (b,s) row; lane j handles mask[b,s,j].
// logp(b,s) = logits[b,s,a] - log( sum_{j: mask_j>0} exp(logits[b,s,mask_j]) )
// No __syncthreads anywhere: tiny 2-warp CTAs maximize resident warps/SM
// (64 vs ~33), doubling per-SM outstanding divergent-gather misses.
__global__ void __launch_bounds__(THREADS) masked_logp_kernel(
    const float* __restrict__ logits,   // [B,S,V] f32
    const int* __restrict__ a,          // [B,S]   i32
    const int* __restrict__ mask,       // [B,S,M] i32
    float* __restrict__ out)            // [B]     f32
{
    const int lane = threadIdx.x & 31;
    const int row  = blockIdx.x * WARPS_PER_BLOCK + (threadIdx.x >> 5);

    const float* __restrict__ lrow = logits + (size_t)row * VV;

    // Action-token chain on lane 0, hoisted to overlap the mask gather round.
    const int ai = (lane == 0) ? __ldg(a + row) : 0;
    float la = 0.0f;
    bool take = false;
    if (lane == 0 && ai != PAD_ID) {
        take = true;
        la = __ldg(lrow + ai);
    }

    // Mask ids (coalesced 128B row), then the scattered 4B gather.
    const int mid = __ldg(mask + (size_t)row * MM + lane);
    const bool valid = (mid > 0);
    float g = valid ? __ldg(lrow + mid) : NEG_INF;

    // Warp max over gathered logits.
    float m = g;
    #pragma unroll
    for (int o = 16; o > 0; o >>= 1)
        m = fmaxf(m, __shfl_xor_sync(0xffffffffu, m, o));

    // Warp sum of exp(g - m) over valid lanes.
    float e = valid ? __expf(g - m) : 0.0f;
    #pragma unroll
    for (int o = 16; o > 0; o >>= 1)
        e += __shfl_xor_sync(0xffffffffu, e, o);

    // Publish this row's logp into a spread partial slot (16 rows/slot ->
    // negligible L2-atomic serialization), then count completion.
    unsigned int prev = 0;
    if (lane == 0) {
        const float logp = take ? (la - (m + __logf(e))) : 0.0f;
        atomicAdd(&g_partials[row >> 4], logp);
        __threadfence();
        prev = atomicAdd(&g_done, 1u);
    }
    const bool last = __shfl_sync(0xffffffffu, prev, 0) == (ROWS - 1);

    // The very last warp to finish folds the 256 slots into out[8] and
    // resets all scratch for the next replay.
    if (last) {
        __threadfence();  // acquire: make all partial atomics visible
        // Slot layout: 32 consecutive slots per batch element (512 rows / 16).
        // Lane l sums slots [l*8, l*8+8), all within b = l/4.
        float v = 0.0f;
        #pragma unroll
        for (int i = 0; i < 8; i++)
            v += g_partials[lane * 8 + i];
        v += __shfl_down_sync(0xffffffffu, v, 2, 4);
        v += __shfl_down_sync(0xffffffffu, v, 1, 4);
        if ((lane & 3) == 0)
            out[lane >> 2] = v;
        // Reset scratch (deterministic across graph replays).
        #pragma unroll
        for (int i = 0; i < 8; i++)
            g_partials[lane * 8 + i] = 0.0f;
        if (lane == 0)
            g_done = 0;
    }
}

extern "C" void kernel_launch(void* const* d_in, const int* in_sizes, int n_in,
                              void* d_out, int out_size) {
    const float* logits = (const float*)d_in[0];  // [8,512,32000] f32
    const int* a        = (const int*)d_in[1];    // [8,512]       i32
    const int* mask     = (const int*)d_in[2];    // [8,512,32]    i32
    float* out = (float*)d_out;                   // [8]           f32

    masked_logp_kernel<<<NBLOCKS, THREADS>>>(logits, a, mask, out);
}